// round 6
// baseline (speedup 1.0000x reference)
#include <cuda_runtime.h>
#include <cuda_bf16.h>
#include <math_constants.h>

#define B 8
#define N 65536
#define C 80
#define T 32
#define MIN_POS 16
#define POSKEY 0x3F000000u   // bits of 0.5f; IoU >= 0 so uint order == float order
#define CH 32                // chunks per image
#define CHK (N / CH)         // 2048 keys per chunk
#define NB (B * CH)          // 256 blocks total (all co-resident)

// ---------------- scratch (device globals; zero-initialized, no allocation) ----
__device__ int      g_maxidx[B * N];
__device__ float    g_sl1[B * N];
__device__ int      g_hist1[B][4096];        // level-1: key>>20
__device__ int      g_h2[B][2][4096];        // level-2: (key>>8)&0xFFF
__device__ int      g_h3[B][2][256];         // level-3 merged
__device__ int      g_h3c[B][CH][2][256];    // level-3 per-chunk (full store)
__device__ int      g_ctl[B][2];             // num_pos, k
__device__ float    g_clspos[B], g_clsneg[B], g_regsum[B];
__device__ int      g_bar[3];
__device__ int      g_done;

// ---------------- helpers ----------------
__device__ __forceinline__ void grid_sync(int ph, int tid)
{
    __syncthreads();
    if (tid == 0) {
        __threadfence();
        atomicAdd(&g_bar[ph], 1);
        while (atomicAdd(&g_bar[ph], 0) < NB) { }
    }
    __syncthreads();
}

// Find digit d such that (#keys in bins > d) < kk <= (#keys in bins >= d).
template <int BINS>
__device__ __forceinline__ void select_digit(const int* __restrict__ h, int kk,
                                             int tid, int lane, int wid,
                                             int* warp_sums, int* sh_out)
{
    constexpr int NT = 512;
    constexpr int V = (BINS + NT - 1) / NT;
    constexpr int NW = NT / 32;
    int loc[V]; int tot = 0;
#pragma unroll
    for (int j = 0; j < V; j++) {
        int bin = tid * V + j;
        loc[j] = (bin < BINS) ? h[bin] : 0;
        tot += loc[j];
    }
    int v = tot;                                   // inclusive suffix within warp
#pragma unroll
    for (int o = 1; o < 32; o <<= 1) {
        int t = __shfl_down_sync(0xffffffffu, v, o);
        if (lane + o < 32) v += t;
    }
    __syncthreads();
    if (lane == 0) warp_sums[wid] = v;
    __syncthreads();
    if (wid == 0) {
        int w = (lane < NW) ? warp_sums[lane] : 0;
#pragma unroll
        for (int o = 1; o < 32; o <<= 1) {
            int t = __shfl_down_sync(0xffffffffu, w, o);
            if (lane + o < 32) w += t;
        }
        if (lane < NW) warp_sums[lane] = w;
    }
    __syncthreads();
    int base = ((wid + 1 < NW) ? warp_sums[wid + 1] : 0) + (v - tot);
    int s = base;
#pragma unroll
    for (int j = V - 1; j >= 0; j--) {
        int sa = s; s += loc[j];
        if (s >= kk && sa < kk) { sh_out[0] = tid * V + j; sh_out[1] = kk - sa; }
    }
    __syncthreads();
}

__device__ __forceinline__ int block_exscan(int v, int lane, int wid, int* warp_sums)
{
    __syncthreads();
    int inc = v;
#pragma unroll
    for (int o = 1; o < 32; o <<= 1) {
        int t = __shfl_up_sync(0xffffffffu, inc, o);
        if (lane >= o) inc += t;
    }
    if (lane == 31) warp_sums[wid] = inc;
    __syncthreads();
    if (wid == 0) {
        int w = (lane < 16) ? warp_sums[lane] : 0;
#pragma unroll
        for (int o = 1; o < 32; o <<= 1) {
            int t = __shfl_up_sync(0xffffffffu, w, o);
            if (lane >= o) w += t;
        }
        if (lane < 16) warp_sums[lane] = w;
    }
    __syncthreads();
    int base = wid ? warp_sums[wid - 1] : 0;
    return base + inc - v;
}

// ---------------- single fused kernel ----------------
__global__ __launch_bounds__(512, 2) void fused_kernel(
    const float* __restrict__ cls, const float* __restrict__ reg,
    const float* __restrict__ anchors, const float* __restrict__ tboxes,
    const int* __restrict__ tlabels, float* __restrict__ out)
{
    __shared__ __align__(16) char smem_raw[32768];
    __shared__ int warp_sums[16];
    __shared__ int s_out[2];
    __shared__ int s_pos;
    __shared__ int s_cnt;
    __shared__ int s_pre[2];
    __shared__ float s_acc[3];

    int b = blockIdx.x / CH, p = blockIdx.x % CH;
    int tid = threadIdx.x, lane = tid & 31, wid = tid >> 5;
    int n0 = p * CHK + tid * 4;
    size_t gbase = (size_t)b * N;

    // ================= Phase 0: decode + IoU (4 anchors/thread) ==============
    float4* sBox = (float4*)smem_raw;
    float*  sAB  = (float*)(smem_raw + T * 16);
    int*    sh0  = (int*)(smem_raw + T * 16 + T * 4);

    if (tid < T) {
        float4 tb = ((const float4*)tboxes)[b * T + tid];
        sBox[tid] = tb;
        sAB[tid] = (tb.z - tb.x) * (tb.w - tb.y);
    }
    for (int j = tid; j < 4096; j += 512) sh0[j] = 0;
    __syncthreads();

    float X1[4], Y1[4], X2[4], Y2[4], AR[4], BI[4], BD[4];
    int BX[4];
#pragma unroll
    for (int c = 0; c < 4; c++) {
        float4 a = ((const float4*)anchors)[n0 + c];
        float4 r = ((const float4*)reg)[gbase + n0 + c];
        float aw = a.z - a.x, ah = a.w - a.y;
        float acx = a.x + 0.5f * aw, acy = a.y + 0.5f * ah;
        float cx = r.x * aw + acx, cy = r.y * ah + acy;
        float w = __expf(r.z) * aw, h = __expf(r.w) * ah;
        X1[c] = cx - 0.5f * w; Y1[c] = cy - 0.5f * h;
        X2[c] = cx + 0.5f * w; Y2[c] = cy + 0.5f * h;
        AR[c] = (X2[c] - X1[c]) * (Y2[c] - Y1[c]);
        BI[c] = 0.f; BD[c] = 1.f; BX[c] = 0;
    }
#pragma unroll 8
    for (int t = 0; t < T; t++) {
        float4 g = sBox[t];
        float ab = sAB[t];
#pragma unroll
        for (int c = 0; c < 4; c++) {
            float lx = fmaxf(X1[c], g.x), ly = fmaxf(Y1[c], g.y);
            float rx = fminf(X2[c], g.z), ry = fminf(Y2[c], g.w);
            float ww = fmaxf(rx - lx, 0.0f), hh = fmaxf(ry - ly, 0.0f);
            float inter = ww * hh;
            float denom = AR[c] + ab - inter + 1e-6f;
            if (inter * BD[c] > BI[c] * denom) { BI[c] = inter; BD[c] = denom; BX[c] = t; }
        }
    }
    unsigned K[4];
#pragma unroll
    for (int c = 0; c < 4; c++) {
        K[c] = __float_as_uint(BI[c] / BD[c]);
        size_t gi = gbase + n0 + c;
        g_maxidx[gi] = BX[c];
        // smooth-L1 (reload anchor/reg — L1-hot)
        float4 a = ((const float4*)anchors)[n0 + c];
        float4 r = ((const float4*)reg)[gi];
        float4 g = sBox[BX[c]];
        float aw = a.z - a.x, ah = a.w - a.y;
        float acx = a.x + 0.5f * aw, acy = a.y + 0.5f * ah;
        float gw_ = g.z - g.x, gh_ = g.w - g.y;
        float gcx = g.x + 0.5f * gw_, gcy = g.y + 0.5f * gh_;
        float t0 = (gcx - acx) / (aw + 1e-6f);
        float t1 = (gcy - acy) / (ah + 1e-6f);
        float t2 = __logf(gw_ / (aw + 1e-6f));
        float t3 = __logf(gh_ / (ah + 1e-6f));
        float d0 = fabsf(r.x - t0), d1 = fabsf(r.y - t1);
        float d2 = fabsf(r.z - t2), d3 = fabsf(r.w - t3);
        float sl = 0.f;
        sl += (d0 < 1.f) ? 0.5f * d0 * d0 : d0 - 0.5f;
        sl += (d1 < 1.f) ? 0.5f * d1 * d1 : d1 - 0.5f;
        sl += (d2 < 1.f) ? 0.5f * d2 * d2 : d2 - 0.5f;
        sl += (d3 < 1.f) ? 0.5f * d3 * d3 : d3 - 0.5f;
        g_sl1[gi] = sl;
        atomicAdd(&sh0[K[c] >> 20], 1);
    }
    __syncthreads();
    for (int j = tid; j < 4096; j += 512) {
        int v = sh0[j];
        if (v) atomicAdd(&g_hist1[b][j], v);
    }
    grid_sync(0, tid);

    // ================= Phase A: level-1 select + level-2 histogram ============
    if (tid == 0) s_pos = 0;
    __syncthreads();
    {
        int possum = 0;
        for (int j = tid; j < 4096; j += 512)
            if (j >= 0x3F0) possum += g_hist1[b][j];
#pragma unroll
        for (int o = 16; o; o >>= 1) possum += __shfl_down_sync(0xffffffffu, possum, o);
        if (lane == 0 && possum) atomicAdd(&s_pos, possum);
    }
    __syncthreads();
    int poscount = s_pos;
    int fb = (poscount < MIN_POS);
    int num_pos = fb ? MIN_POS : poscount;
    int k = min(N - num_pos, 4 * num_pos);

    select_digit<4096>(g_hist1[b], MIN_POS, tid, lane, wid, warp_sums, s_out);
    int d16 = s_out[0], rem16 = s_out[1];
    select_digit<4096>(g_hist1[b], k + num_pos, tid, lane, wid, warp_sums, s_out);
    int dN = s_out[0], remN = s_out[1];

    if (p == 0) {
        if (tid == 0) {
            g_ctl[b][0] = num_pos; g_ctl[b][1] = k;
            g_clspos[b] = 0.f; g_clsneg[b] = 0.f; g_regsum[b] = 0.f;
        }
        ((int*)g_h3[b])[tid] = 0;                      // 512 ints exactly
    }

    int* sh2 = (int*)smem_raw;                         // 2 x 4096
    for (int i = tid; i < 8192; i += 512) sh2[i] = 0;
    __syncthreads();
#pragma unroll
    for (int c = 0; c < 4; c++) {
        unsigned key = K[c];
        int hi = (int)(key >> 20);
        if (hi == d16) atomicAdd(&sh2[(key >> 8) & 0xFFF], 1);
        if (hi == dN)  atomicAdd(&sh2[4096 + ((key >> 8) & 0xFFF)], 1);
    }
    __syncthreads();
    for (int i = tid; i < 8192; i += 512) {
        int v = sh2[i];
        if (v) atomicAdd(&((int*)g_h2[b])[i], v);
    }
    grid_sync(1, tid);

    // ================= Phase B: level-2 select + level-3 histogram ============
    select_digit<4096>(g_h2[b][0], rem16, tid, lane, wid, warp_sums, s_out);
    int p24_16 = (d16 << 12) | s_out[0]; int rem2_16 = s_out[1];
    select_digit<4096>(g_h2[b][1], remN, tid, lane, wid, warp_sums, s_out);
    int p24_N = (dN << 12) | s_out[0]; int rem2_N = s_out[1];

    int* sh3 = (int*)smem_raw;                         // 2 x 256
    sh3[tid] = 0;                                      // wait: only 512 ints needed
    __syncthreads();
#pragma unroll
    for (int c = 0; c < 4; c++) {
        unsigned key = K[c];
        int hi = (int)(key >> 8);
        if (hi == p24_16) atomicAdd(&sh3[key & 0xFF], 1);
        if (hi == p24_N)  atomicAdd(&sh3[256 + (key & 0xFF)], 1);
    }
    __syncthreads();
    {
        int v = sh3[tid];
        ((int*)g_h3c[b][p])[tid] = v;                  // full store, no clear
        if (v) atomicAdd(&((int*)g_h3[b])[tid], v);
    }
    grid_sync(2, tid);

    // ================= Phase C: final tau + selection + loss ==================
    unsigned* sl_list = (unsigned*)smem_raw;           // CHK entries
    int* slab = (int*)(smem_raw + CHK * 4);
    if (tid == 0) s_cnt = 0;
    if (tid < 3) s_acc[tid] = 0.f;
    if (tid < T) slab[tid] = tlabels[b * T + tid];

    // clear level-1/level-2 hists for next call (nobody reads them in phase C)
    {
        int gid = blockIdx.x * 512 + tid;
        int stride = NB * 512;
        for (int i = gid; i < B * 4096; i += stride) ((int*)g_hist1)[i] = 0;
        for (int i = gid; i < B * 2 * 4096; i += stride) ((int*)g_h2)[i] = 0;
    }

    select_digit<256>(g_h3[b][0], rem2_16, tid, lane, wid, warp_sums, s_out);
    int lb16 = s_out[0], m16 = s_out[1];
    unsigned tau16 = ((unsigned)p24_16 << 8) | (unsigned)lb16;
    select_digit<256>(g_h3[b][1], rem2_N, tid, lane, wid, warp_sums, s_out);
    int lbN = s_out[0], mN = s_out[1];
    unsigned tauN = ((unsigned)p24_N << 8) | (unsigned)lbN;

    if (wid == 0) {
        int v16 = (lane < p && fb) ? g_h3c[b][lane][0][lb16] : 0;
        int vN  = (lane < p)       ? g_h3c[b][lane][1][lbN]  : 0;
#pragma unroll
        for (int o = 16; o; o >>= 1) {
            v16 += __shfl_down_sync(0xffffffffu, v16, o);
            vN  += __shfl_down_sync(0xffffffffu, vN, o);
        }
        if (lane == 0) { s_pre[0] = v16; s_pre[1] = vN; }
    }
    __syncthreads();
    int pre16 = s_pre[0], preN = s_pre[1];

    int r16 = 0;
    if (fb) {
        int c16 = (K[0] == tau16) + (K[1] == tau16) + (K[2] == tau16) + (K[3] == tau16);
        r16 = pre16 + block_exscan(c16, lane, wid, warp_sums);
    }
    int cN = (K[0] == tauN) + (K[1] == tauN) + (K[2] == tauN) + (K[3] == tauN);
    int rN = preN + block_exscan(cN, lane, wid, warp_sums);

#pragma unroll
    for (int c = 0; c < 4; c++) {
        unsigned key = K[c];
        bool eq16 = fb && (key == tau16);
        bool pos = fb ? (key > tau16 || (eq16 && r16 < m16)) : (key >= POSKEY);
        if (eq16) r16++;
        bool neg = false;
        if (!pos) {
            if (key > tauN) neg = true;
            else if (key == tauN) neg = (rN < mN);     // rank over ALL ties
        }
        if (key == tauN) rN++;
        if (pos | neg) {
            int slot = atomicAdd(&s_cnt, 1);
            unsigned idx = (unsigned)(n0 + c);
            sl_list[slot] = idx | (pos ? 0x80000000u : 0u);
        }
    }
    __syncthreads();
    int cnt = s_cnt;

    // ---- loss (2 anchors per warp-iteration for ILP) ----
    float ap = 0.f, an = 0.f, ar = 0.f;
    for (int j0 = wid * 2; j0 < cnt; j0 += 32) {
        unsigned e0 = sl_list[j0];
        int has1 = (j0 + 1 < cnt);
        unsigned e1 = sl_list[has1 ? j0 + 1 : j0];
        int ip0 = (int)(e0 >> 31), ip1 = (int)(e1 >> 31);
        size_t gi0 = gbase + (e0 & 0x7FFFFFFFu);
        size_t gi1 = gbase + (e1 & 0x7FFFFFFFu);
        const float* r0 = cls + gi0 * C;
        const float* r1 = cls + gi1 * C;

        int mi0 = 0, mi1 = 0; float q0 = 0.f, q1 = 0.f;
        if (ip0) { mi0 = g_maxidx[gi0]; q0 = g_sl1[gi0]; }
        if (ip1) { mi1 = g_maxidx[gi1]; q1 = g_sl1[gi1]; }

        float a0 = r0[lane], b0 = r0[lane + 32], c0 = (lane < 16) ? r0[lane + 64] : 0.f;
        float a1 = r1[lane], b1 = r1[lane + 32], c1 = (lane < 16) ? r1[lane + 64] : 0.f;
        float s0 = __expf(a0) + __expf(b0) + ((lane < 16) ? __expf(c0) : 0.f);
        float s1 = __expf(a1) + __expf(b1) + ((lane < 16) ? __expf(c1) : 0.f);
#pragma unroll
        for (int o = 16; o; o >>= 1) {
            s0 += __shfl_xor_sync(0xffffffffu, s0, o);
            s1 += __shfl_xor_sync(0xffffffffu, s1, o);
        }
        float l0 = __logf(s0), l1 = __logf(s1);

        float xl0 = 0.f, xl1 = 0.f;
        if (ip0) {
            int lb = slab[mi0];
            xl0 = (lb < 32) ? __shfl_sync(0xffffffffu, a0, lb)
                : (lb < 64) ? __shfl_sync(0xffffffffu, b0, lb - 32)
                            : __shfl_sync(0xffffffffu, c0, lb - 64);
        }
        if (ip1) {
            int lb = slab[mi1];
            xl1 = (lb < 32) ? __shfl_sync(0xffffffffu, a1, lb)
                : (lb < 64) ? __shfl_sync(0xffffffffu, b1, lb - 32)
                            : __shfl_sync(0xffffffffu, c1, lb - 64);
        }
        if (lane == 0) {
            if (ip0) {
                float ce = l0 - xl0;
                float pp = __expf(-ce), om = 1.f - pp;
                ap += 0.25f * om * om * ce;
                ar += q0;
            } else {
                float ce = l0 - a0;
                float pp = __expf(-ce), om = 1.f - pp;
                an += 0.9f * om * om * om * ce;
            }
            if (has1) {
                if (ip1) {
                    float ce = l1 - xl1;
                    float pp = __expf(-ce), om = 1.f - pp;
                    ap += 0.25f * om * om * ce;
                    ar += q1;
                } else {
                    float ce = l1 - a1;
                    float pp = __expf(-ce), om = 1.f - pp;
                    an += 0.9f * om * om * om * ce;
                }
            }
        }
    }
    if (lane == 0 && (ap != 0.f || an != 0.f || ar != 0.f)) {
        atomicAdd(&s_acc[0], ap);
        atomicAdd(&s_acc[1], an);
        atomicAdd(&s_acc[2], ar);
    }
    __syncthreads();
    if (tid == 0 && s_acc[0] != 0.f) atomicAdd(&g_clspos[b], s_acc[0]);
    if (tid == 1 && s_acc[1] != 0.f) atomicAdd(&g_clsneg[b], s_acc[1]);
    if (tid == 2 && s_acc[2] != 0.f) atomicAdd(&g_regsum[b], s_acc[2]);
    __threadfence();
    __syncthreads();

    if (tid == 0) {
        int prev = atomicAdd(&g_done, 1);
        if (prev == NB - 1) {                          // last block: final outputs
            float cls_sum = 0.f, reg_sum = 0.f;
            int tp = 0;
            for (int bb = 0; bb < B; bb++) {
                int np = g_ctl[bb][0], nn = g_ctl[bb][1];
                cls_sum += (g_clspos[bb] + g_clsneg[bb]) / (float)max(np + nn, 1);
                reg_sum += g_regsum[bb] / ((float)np + 1e-6f);
                tp += np;
            }
            float cls_final = cls_sum / (float)B;
            float reg_final = (tp > 0) ? (reg_sum / (float)B) : 0.f;
            float rw = fminf(1.f, (float)tp / (100.f * (float)B));
            out[0] = cls_final + rw * 1.0f * reg_final;
            out[1] = cls_final;
            out[2] = reg_final;
            out[3] = (float)tp;
            g_bar[0] = 0; g_bar[1] = 0; g_bar[2] = 0;  // reset for next replay
            __threadfence();
            atomicExch(&g_done, 0);
        }
    }
}

// ---------------- launch ----------------
extern "C" void kernel_launch(void* const* d_in, const int* in_sizes, int n_in,
                              void* d_out, int out_size)
{
    const float* cls     = (const float*)d_in[0];
    const float* reg     = (const float*)d_in[1];
    const float* anchors = (const float*)d_in[2];
    const float* tboxes  = (const float*)d_in[3];
    const int*   tlabels = (const int*)d_in[4];
    float* out = (float*)d_out;

    fused_kernel<<<NB, 512>>>(cls, reg, anchors, tboxes, tlabels, out);
}